// round 8
// baseline (speedup 1.0000x reference)
#include <cuda_runtime.h>
#include <cuda_bf16.h>
#include <cstdint>
#include <cstddef>

// Problem constants
#define NUM_STATE 2048
#define BATCH     4096

// ---------------------------------------------------------------------------
// Scratch (device globals; no cudaMalloc allowed)
// ---------------------------------------------------------------------------
__device__ __align__(16) __nv_bfloat16 g_alphaB[(size_t)BATCH * NUM_STATE];     // 16 MB
__device__ __align__(16) __nv_bfloat16 g_matT[(size_t)NUM_STATE * NUM_STATE];   // 8 MB, matT[t][s] = mat[s][t]
__device__ float g_rmax[NUM_STATE];
__device__ float g_rinv[NUM_STATE];

// Producer/consumer flags (zeroed by zero_flags_kernel each launch)
#define NSLABS 32
__device__ int g_stats_cnt[NSLABS];   // rows of stats done per slab (target 64)
__device__ int g_alpha_cnt[NSLABS];   // alpha cvt tiles done per slab (target 32)
__device__ int g_mat_cnt[NSLABS];     // matT build tiles done per slab (target 128)

// ---------------------------------------------------------------------------
// Helpers
// ---------------------------------------------------------------------------
__device__ __forceinline__ uint32_t smem_u32(const void* p) {
    uint32_t a;
    asm("{ .reg .u64 t; cvta.to.shared.u64 t, %1; cvt.u32.u64 %0, t; }" : "=r"(a) : "l"(p));
    return a;
}

#define SWZ128(off) ((off) ^ (((off) >> 3) & 0x70))

__device__ __forceinline__ void cp_async16(uint32_t s, const void* g) {
    asm volatile("cp.async.cg.shared.global [%0], [%1], 16;" :: "r"(s), "l"(g) : "memory");
}
#define CP_COMMIT() asm volatile("cp.async.commit_group;" ::: "memory")
template <int N>
__device__ __forceinline__ void cp_wait() {
    asm volatile("cp.async.wait_group %0;" :: "n"(N) : "memory");
}

__device__ __forceinline__ void ldsm4(uint32_t* r, uint32_t addr) {
    asm volatile("ldmatrix.sync.aligned.m8n8.x4.shared.b16 {%0,%1,%2,%3}, [%4];"
                 : "=r"(r[0]), "=r"(r[1]), "=r"(r[2]), "=r"(r[3]) : "r"(addr));
}

__device__ __forceinline__ void mma_bf16(float* c, const uint32_t* a,
                                         uint32_t b0, uint32_t b1) {
    asm volatile(
        "mma.sync.aligned.m16n8k16.row.col.f32.bf16.bf16.f32 "
        "{%0,%1,%2,%3}, {%4,%5,%6,%7}, {%8,%9}, {%0,%1,%2,%3};"
        : "+f"(c[0]), "+f"(c[1]), "+f"(c[2]), "+f"(c[3])
        : "r"(a[0]), "r"(a[1]), "r"(a[2]), "r"(a[3]), "r"(b0), "r"(b1));
}

// ---------------------------------------------------------------------------
// Work decomposition (slab-ordered so GEMM can consume K-slabs as produced)
//   per slab k (64 K-columns): 64 stats rows + 32 alpha-cvt tiles + 128 build
// ---------------------------------------------------------------------------
static constexpr int NPREP = 160;                 // dedicated prep CTAs (wave-1 resident)
static constexpr int ITEMS_PER_SLAB = 64 + 32 + 128;   // 224
static constexpr int NITEMS = ITEMS_PER_SLAB * NSLABS; // 7168
static constexpr int GEMM_TILES = (BATCH / 128) * (NUM_STATE / 128);  // 512

__global__ void zero_flags_kernel() {
    const int i = threadIdx.x;
    if (i < NSLABS) { g_stats_cnt[i] = 0; g_alpha_cnt[i] = 0; g_mat_cnt[i] = 0; }
}

// ---------------------------------------------------------------------------
// Prep item bodies (256 threads each). Each ends with __threadfence + counter.
// ---------------------------------------------------------------------------
__device__ __forceinline__ void stats_item(const float* __restrict__ utm, int s,
                                           int slab, float* s_red, float* s_bcast) {
    const float* row = utm + (size_t)s * (NUM_STATE - 1);
    const int tid = threadIdx.x;
    const int base = tid * 8;

    float v[8];
    #pragma unroll
    for (int j = 0; j < 8; j++)
        v[j] = (base + j < NUM_STATE - 1) ? row[base + j] : -3.4e38f;

    float mx = v[0];
    #pragma unroll
    for (int j = 1; j < 8; j++) mx = fmaxf(mx, v[j]);
    #pragma unroll
    for (int o = 16; o; o >>= 1) mx = fmaxf(mx, __shfl_xor_sync(0xffffffffu, mx, o));
    if ((tid & 31) == 0) s_red[tid >> 5] = mx;
    __syncthreads();
    if (tid == 0) {
        float m = s_red[0];
        #pragma unroll
        for (int i = 1; i < 8; i++) m = fmaxf(m, s_red[i]);
        *s_bcast = m;
    }
    __syncthreads();
    const float m = *s_bcast;

    float sm = 0.f;
    #pragma unroll
    for (int j = 0; j < 8; j++)
        if (base + j < NUM_STATE - 1) sm += __expf(v[j] - m);
    #pragma unroll
    for (int o = 16; o; o >>= 1) sm += __shfl_xor_sync(0xffffffffu, sm, o);
    if ((tid & 31) == 0) s_red[tid >> 5] = sm;
    __syncthreads();
    if (tid == 0) {
        float t = 0.f;
        #pragma unroll
        for (int i = 0; i < 8; i++) t += s_red[i];
        g_rmax[s] = m;
        g_rinv[s] = 1.0f / t;
        __threadfence();
        atomicAdd(&g_stats_cnt[slab], 1);
    }
}

// Convert alpha[128 rows x 64 cols] (rows 128*j.., cols 64*slab..) to bf16.
__device__ __forceinline__ void cvt_item(const float* __restrict__ alpha,
                                         int slab, int j) {
    const int tid = threadIdx.x;
    const int k0 = slab * 64;
    #pragma unroll
    for (int jj = 0; jj < 8; jj++) {
        const int idx = tid + jj * 256;            // 0..2047
        const int row = 128 * j + (idx >> 4);
        const int col = k0 + (idx & 15) * 4;
        const size_t off = (size_t)row * NUM_STATE + col;
        const float4 v = *reinterpret_cast<const float4*>(alpha + off);
        __nv_bfloat162 p0 = __floats2bfloat162_rn(v.x, v.y);
        __nv_bfloat162 p1 = __floats2bfloat162_rn(v.z, v.w);
        uint2 w;
        w.x = *reinterpret_cast<uint32_t*>(&p0);
        w.y = *reinterpret_cast<uint32_t*>(&p1);
        *reinterpret_cast<uint2*>(&g_alphaB[off]) = w;
    }
    __syncthreads();
    if (tid == 0) { __threadfence(); atomicAdd(&g_alpha_cnt[slab], 1); }
}

// Build matT[t0..t0+32)[s0..s0+32). Requires stats for the whole slab.
__device__ __forceinline__ void build_item(const float* __restrict__ utm,
                                           int slab, int shalf, int tblk,
                                           float (*su)[34]) {
    const int tid = threadIdx.x;
    if (tid == 0) {
        while (*(volatile int*)&g_stats_cnt[slab] < 64) { }
    }
    __syncthreads();

    const int s0 = slab * 64 + shalf * 32;
    const int t0 = tblk * 32;
    const int tx = tid & 31;       // -> s
    const int ty = tid >> 5;       // -> t (x4)

    for (int i = tid; i < 32 * 33; i += 256) {
        const int sy = i / 33;
        const int cx = i % 33;
        const int c = t0 - 1 + cx;
        su[sy][cx] = (c >= 0 && c < NUM_STATE - 1)
                       ? utm[(size_t)(s0 + sy) * (NUM_STATE - 1) + c] : 0.f;
    }
    __syncthreads();

    const int s = s0 + tx;
    const float mx = g_rmax[s];
    const float inv = g_rinv[s];

    #pragma unroll
    for (int k = 0; k < 4; k++) {
        const int yy = ty + 8 * k;
        const int t = t0 + yy;
        float v;
        if (t == s) {
            v = 0.f;
        } else {
            const int cx = yy + 1 - (t > s);   // = (t - (t>s)) - (t0-1)
            v = __expf(su[tx][cx] - mx) * inv;
        }
        g_matT[(size_t)t * NUM_STATE + s] = __float2bfloat16(v);
    }
    __syncthreads();
    if (tid == 0) { __threadfence(); atomicAdd(&g_mat_cnt[slab], 1); }
}

// ---------------------------------------------------------------------------
// Megakernel: blocks [0, NPREP) produce (slab-ordered, static stride — no
// atomics on the work list, deterministic); blocks [NPREP, NPREP+512) are the
// GEMM, gated per K-slab on the completion counters.
// GEMM config identical to R5-R7 (at the legacy-HMMA issue ceiling).
// ---------------------------------------------------------------------------
static constexpr int BM = 128, BN = 128, BK = 64, STAGES = 3;
static constexpr int KITERS = NUM_STATE / BK;                       // 32 == NSLABS
static constexpr int TILE_BYTES = BM * BK * 2;                      // 16384 (128B/row)
static constexpr int STAGE_BYTES = 2 * TILE_BYTES;                  // 32768
static constexpr int DYN_SMEM = STAGES * STAGE_BYTES + 1024;        // 99328

__global__ __launch_bounds__(256, 2) void mega_kernel(const float* __restrict__ utm,
                                                      const float* __restrict__ alpha,
                                                      float* __restrict__ out) {
    extern __shared__ char dsm[];
    __shared__ float s_red[8];
    __shared__ float s_bcast;
    __shared__ float s_su[32][34];

    const int tid = threadIdx.x;
    const int bid = blockIdx.x;

    // ---------------- Prep role ----------------
    if (bid < NPREP) {
        for (int item = bid; item < NITEMS; item += NPREP) {
            const int slab = item / ITEMS_PER_SLAB;
            const int r = item % ITEMS_PER_SLAB;
            if (r < 64) {
                stats_item(utm, slab * 64 + r, slab, s_red, &s_bcast);
            } else if (r < 96) {
                cvt_item(alpha, slab, r - 64);
            } else {
                build_item(utm, slab, (r - 96) & 1, (r - 96) >> 1, s_su);
            }
            __syncthreads();   // protect shared scratch reuse across items
        }
        return;
    }

    // ---------------- GEMM role ----------------
    const uint32_t dyn_base = (smem_u32(dsm) + 1023u) & ~1023u;
    const int wid = tid >> 5;
    const int lane = tid & 31;

    const int tile = bid - NPREP;
    const int n0 = (tile & 15) * BN;
    const int m0 = (tile >> 4) * BM;

    const int warp_m = wid & 3;
    const int warp_n = wid >> 2;
    const int lrow = lane & 15;
    const int lcol16 = (lane >> 4) & 1;

    uint32_t aswz[2], bswz[4];
    #pragma unroll
    for (int mi = 0; mi < 2; mi++)
        aswz[mi] = SWZ128((uint32_t)((warp_m * 32 + mi * 16 + lrow) * 128 + lcol16 * 16));
    #pragma unroll
    for (int nj = 0; nj < 4; nj++)
        bswz[nj] = SWZ128((uint32_t)((warp_n * 64 + nj * 16 + lrow) * 128 + lcol16 * 16));

    auto wait_slab = [&](int k) {
        if (tid == 0) {
            while (*(volatile int*)&g_alpha_cnt[k] < 32 ||
                   *(volatile int*)&g_mat_cnt[k]   < 128) { }
            __threadfence();
        }
        __syncthreads();
    };

    auto load_stage = [&](int kit) {
        const int buf = kit % STAGES;
        const uint32_t sA = dyn_base + buf * STAGE_BYTES;
        const uint32_t sB = sA + TILE_BYTES;
        const int k0 = kit * BK;
        #pragma unroll
        for (int r = 0; r < 4; r++) {
            const int idx = tid + r * 256;
            const int row = idx >> 3;
            const int c16 = idx & 7;
            const uint32_t soff = SWZ128((uint32_t)(row * 128 + c16 * 16));
            cp_async16(sA + soff, &g_alphaB[(size_t)(m0 + row) * NUM_STATE + k0 + c16 * 8]);
            cp_async16(sB + soff, &g_matT [(size_t)(n0 + row) * NUM_STATE + k0 + c16 * 8]);
        }
    };

    float c[2][8][4];
    #pragma unroll
    for (int i = 0; i < 2; i++)
        #pragma unroll
        for (int j = 0; j < 8; j++)
            #pragma unroll
            for (int k = 0; k < 4; k++) c[i][j][k] = 0.f;

    uint32_t af[2][4], bf[4][4];

    auto ldsm_ks = [&](uint32_t sA, uint32_t sB, int ks) {
        const uint32_t kx = (uint32_t)(ks << 5);
        #pragma unroll
        for (int mi = 0; mi < 2; mi++) ldsm4(af[mi], sA + (aswz[mi] ^ kx));
        #pragma unroll
        for (int nj = 0; nj < 4; nj++) ldsm4(bf[nj], sB + (bswz[nj] ^ kx));
    };
    auto mma_all = [&]() {
        #pragma unroll
        for (int mi = 0; mi < 2; mi++)
            #pragma unroll
            for (int nj = 0; nj < 4; nj++) {
                mma_bf16(c[mi][nj * 2 + 0], af[mi], bf[nj][0], bf[nj][2]);
                mma_bf16(c[mi][nj * 2 + 1], af[mi], bf[nj][1], bf[nj][3]);
            }
    };

    // Prologue: gated on the first two slabs
    #pragma unroll
    for (int i = 0; i < STAGES - 1; i++) {
        wait_slab(i);
        load_stage(i);
        CP_COMMIT();
    }

    for (int kit = 0; kit < KITERS; kit++) {
        cp_wait<STAGES - 2>();
        __syncthreads();

        const uint32_t sA = dyn_base + (kit % STAGES) * STAGE_BYTES;
        const uint32_t sB = sA + TILE_BYTES;

        ldsm_ks(sA, sB, 0);
        if (kit + STAGES - 1 < KITERS) {
            wait_slab(kit + STAGES - 1);
            load_stage(kit + STAGES - 1);
        }
        CP_COMMIT();

        #pragma unroll
        for (int ks = 0; ks < BK / 16; ks++) {
            mma_all();
            if (ks < BK / 16 - 1) ldsm_ks(sA, sB, ks + 1);
        }
    }

    const int r_base = m0 + warp_m * 32 + (lane >> 2);
    const int c_base = n0 + warp_n * 64 + (lane & 3) * 2;
    #pragma unroll
    for (int mi = 0; mi < 2; mi++) {
        #pragma unroll
        for (int ni = 0; ni < 8; ni++) {
            float* p0 = out + (size_t)(r_base + mi * 16) * NUM_STATE + c_base + ni * 8;
            float* p1 = out + (size_t)(r_base + mi * 16 + 8) * NUM_STATE + c_base + ni * 8;
            *reinterpret_cast<float2*>(p0) = make_float2(c[mi][ni][0], c[mi][ni][1]);
            *reinterpret_cast<float2*>(p1) = make_float2(c[mi][ni][2], c[mi][ni][3]);
        }
    }
}

// ---------------------------------------------------------------------------
// Launch
// ---------------------------------------------------------------------------
extern "C" void kernel_launch(void* const* d_in, const int* in_sizes, int n_in,
                              void* d_out, int out_size) {
    (void)in_sizes; (void)n_in; (void)out_size;
    // metadata order: state_embeddings(0, unused), alpha(1), context(2, unused), utm(3)
    const float* alpha = (const float*)d_in[1];
    const float* utm   = (const float*)d_in[3];
    float* out = (float*)d_out;

    cudaFuncSetAttribute(mega_kernel, cudaFuncAttributeMaxDynamicSharedMemorySize, DYN_SMEM);

    zero_flags_kernel<<<1, 32>>>();
    mega_kernel<<<NPREP + GEMM_TILES, 256, DYN_SMEM>>>(utm, alpha, out);
}

// round 10
// speedup vs baseline: 2.1027x; 2.1027x over previous
#include <cuda_runtime.h>
#include <cuda_bf16.h>
#include <cstdint>
#include <cstddef>

// Problem constants
#define NUM_STATE 2048
#define BATCH     4096

// ---------------------------------------------------------------------------
// Scratch (device globals; no cudaMalloc allowed)
// ---------------------------------------------------------------------------
__device__ __align__(16) __nv_bfloat16 g_alphaB[(size_t)BATCH * NUM_STATE];     // 16 MB
__device__ __align__(16) __nv_bfloat16 g_matT[(size_t)NUM_STATE * NUM_STATE];   // 8 MB, matT[t][s] = mat[s][t]
__device__ float g_rmax[NUM_STATE];
__device__ float g_rinv[NUM_STATE];

// Per-32-row stats completion counters (zeroed each launch by zero_flags_kernel)
#define NGROUPS 64   // 2048 rows / 32
__device__ int g_stats_cnt[NGROUPS];   // target 32 rows per group

// ---------------------------------------------------------------------------
// Helpers
// ---------------------------------------------------------------------------
__device__ __forceinline__ uint32_t smem_u32(const void* p) {
    uint32_t a;
    asm("{ .reg .u64 t; cvta.to.shared.u64 t, %1; cvt.u32.u64 %0, t; }" : "=r"(a) : "l"(p));
    return a;
}

#define SWZ128(off) ((off) ^ (((off) >> 3) & 0x70))

__device__ __forceinline__ void cp_async16(uint32_t s, const void* g) {
    asm volatile("cp.async.cg.shared.global [%0], [%1], 16;" :: "r"(s), "l"(g) : "memory");
}
#define CP_COMMIT() asm volatile("cp.async.commit_group;" ::: "memory")
template <int N>
__device__ __forceinline__ void cp_wait() {
    asm volatile("cp.async.wait_group %0;" :: "n"(N) : "memory");
}

__device__ __forceinline__ void ldsm4(uint32_t* r, uint32_t addr) {
    asm volatile("ldmatrix.sync.aligned.m8n8.x4.shared.b16 {%0,%1,%2,%3}, [%4];"
                 : "=r"(r[0]), "=r"(r[1]), "=r"(r[2]), "=r"(r[3]) : "r"(addr));
}

__device__ __forceinline__ void mma_bf16(float* c, const uint32_t* a,
                                         uint32_t b0, uint32_t b1) {
    asm volatile(
        "mma.sync.aligned.m16n8k16.row.col.f32.bf16.bf16.f32 "
        "{%0,%1,%2,%3}, {%4,%5,%6,%7}, {%8,%9}, {%0,%1,%2,%3};"
        : "+f"(c[0]), "+f"(c[1]), "+f"(c[2]), "+f"(c[3])
        : "r"(a[0]), "r"(a[1]), "r"(a[2]), "r"(a[3]), "r"(b0), "r"(b1));
}

// ---------------------------------------------------------------------------
// Prep block roles, dispatched in-order within ONE kernel:
//   [0, 2048)            stats rows (never wait)
//   [2048, 3072)         alpha cvt chunks (never wait)
//   [3072, 7168)         matT build tiles (spin on the 32-row stats group
//                        they read; producers were dispatched >=1024 blocks
//                        earlier and never wait themselves -> deadlock-free)
// ---------------------------------------------------------------------------
static constexpr int STATS_BLOCKS = NUM_STATE;                              // 2048
static constexpr int CVT_CHUNK = 8192;
static constexpr int CVT_CHUNKS = (BATCH * NUM_STATE) / CVT_CHUNK;          // 1024
static constexpr int BUILD_BLOCKS = (NUM_STATE / 32) * (NUM_STATE / 32);    // 4096
static constexpr int PREP_BLOCKS = STATS_BLOCKS + CVT_CHUNKS + BUILD_BLOCKS;

__global__ void zero_flags_kernel() {
    if (threadIdx.x < NGROUPS) g_stats_cnt[threadIdx.x] = 0;
}

__global__ __launch_bounds__(256) void prep_kernel(const float* __restrict__ utm,
                                                   const float* __restrict__ alpha) {
    const int bid = blockIdx.x;
    const int tid = threadIdx.x;

    if (bid < STATS_BLOCKS) {
        // ---- stats for row s: register-resident, MLP 8 ----
        const int s = bid;
        const float* row = utm + (size_t)s * (NUM_STATE - 1);
        const int base = tid * 8;

        __shared__ float red[8];
        __shared__ float s_mx;

        float v[8];
        #pragma unroll
        for (int j = 0; j < 8; j++)
            v[j] = (base + j < NUM_STATE - 1) ? row[base + j] : -3.4e38f;

        float mx = v[0];
        #pragma unroll
        for (int j = 1; j < 8; j++) mx = fmaxf(mx, v[j]);
        #pragma unroll
        for (int o = 16; o; o >>= 1) mx = fmaxf(mx, __shfl_xor_sync(0xffffffffu, mx, o));
        if ((tid & 31) == 0) red[tid >> 5] = mx;
        __syncthreads();
        if (tid == 0) {
            float m = red[0];
            #pragma unroll
            for (int i = 1; i < 8; i++) m = fmaxf(m, red[i]);
            s_mx = m;
        }
        __syncthreads();
        const float m = s_mx;

        float sm = 0.f;
        #pragma unroll
        for (int j = 0; j < 8; j++)
            if (base + j < NUM_STATE - 1) sm += __expf(v[j] - m);
        #pragma unroll
        for (int o = 16; o; o >>= 1) sm += __shfl_xor_sync(0xffffffffu, sm, o);
        if ((tid & 31) == 0) red[tid >> 5] = sm;
        __syncthreads();
        if (tid == 0) {
            float t = 0.f;
            #pragma unroll
            for (int i = 0; i < 8; i++) t += red[i];
            g_rmax[s] = m;
            g_rinv[s] = 1.0f / t;
            __threadfence();
            atomicAdd(&g_stats_cnt[s >> 5], 1);
        }
        return;
    }

    if (bid < STATS_BLOCKS + CVT_CHUNKS) {
        // ---- alpha fp32 -> bf16, 8192 contiguous elements, MLP 8 ----
        const int cb = bid - STATS_BLOCKS;
        const size_t base = (size_t)cb * CVT_CHUNK + tid * 4;
        float4 v[8];
        #pragma unroll
        for (int j = 0; j < 8; j++)
            v[j] = *reinterpret_cast<const float4*>(alpha + base + (size_t)j * 1024);
        #pragma unroll
        for (int j = 0; j < 8; j++) {
            __nv_bfloat162 p0 = __floats2bfloat162_rn(v[j].x, v[j].y);
            __nv_bfloat162 p1 = __floats2bfloat162_rn(v[j].z, v[j].w);
            uint2 w;
            w.x = *reinterpret_cast<uint32_t*>(&p0);
            w.y = *reinterpret_cast<uint32_t*>(&p1);
            *reinterpret_cast<uint2*>(&g_alphaB[base + (size_t)j * 1024]) = w;
        }
        return;
    }

    // ---- build matT tile [t0..t0+32) x [s0..s0+32) ----
    const int idx = bid - STATS_BLOCKS - CVT_CHUNKS;
    const int s0 = (idx & 63) * 32;
    const int t0 = (idx >> 6) * 32;

    // Gate on this tile's 32 stats rows (group s0/32). nanosleep keeps the
    // spinner from hogging issue slots of co-resident producer blocks.
    if (tid == 0) {
        while (*(volatile int*)&g_stats_cnt[s0 >> 5] < 32) { __nanosleep(32); }
        __threadfence();
    }
    __syncthreads();

    const int tx = tid & 31;        // -> s
    const int ty = tid >> 5;        // -> t (x4)

    __shared__ float su[32][34];    // su[sy][cx] = u[s0+sy][t0-1+cx]

    for (int i = tid; i < 32 * 33; i += 256) {
        const int sy = i / 33;
        const int cx = i % 33;
        const int c = t0 - 1 + cx;
        su[sy][cx] = (c >= 0 && c < NUM_STATE - 1)
                       ? utm[(size_t)(s0 + sy) * (NUM_STATE - 1) + c] : 0.f;
    }
    __syncthreads();

    const int s = s0 + tx;
    const float mx = g_rmax[s];
    const float inv = g_rinv[s];

    #pragma unroll
    for (int k = 0; k < 4; k++) {
        const int yy = ty + 8 * k;
        const int t = t0 + yy;
        float v;
        if (t == s) {
            v = 0.f;
        } else {
            const int cx = yy + 1 - (t > s);   // = (t - (t>s)) - (t0-1)
            v = __expf(su[tx][cx] - mx) * inv;
        }
        g_matT[(size_t)t * NUM_STATE + s] = __float2bfloat16(v);
    }
}

// ---------------------------------------------------------------------------
// GEMM: mma.sync bf16, C[4096,2048] = A @ matT^T  (frozen since R5; at the
// legacy-HMMA issue ceiling ~16 cyc/HMMA/SMSP).
// CTA tile 128x128x64, 3-stage cp.async pipeline, 8 warps (4x2), 2 CTAs/SM.
// ---------------------------------------------------------------------------
static constexpr int BM = 128, BN = 128, BK = 64, STAGES = 3;
static constexpr int KITERS = NUM_STATE / BK;                       // 32
static constexpr int TILE_BYTES = BM * BK * 2;                      // 16384 (128B/row)
static constexpr int STAGE_BYTES = 2 * TILE_BYTES;                  // 32768
static constexpr int DYN_SMEM = STAGES * STAGE_BYTES + 1024;        // 99328

__global__ __launch_bounds__(256, 2) void gemm_kernel(float* __restrict__ out) {
    extern __shared__ char dsm[];
    const uint32_t dyn_base = (smem_u32(dsm) + 1023u) & ~1023u;

    const int tid = threadIdx.x;
    const int wid = tid >> 5;
    const int lane = tid & 31;

    const int tile = blockIdx.x;
    const int n0 = (tile & 15) * BN;
    const int m0 = (tile >> 4) * BM;

    const int warp_m = wid & 3;
    const int warp_n = wid >> 2;
    const int lrow = lane & 15;
    const int lcol16 = (lane >> 4) & 1;

    uint32_t aswz[2], bswz[4];
    #pragma unroll
    for (int mi = 0; mi < 2; mi++)
        aswz[mi] = SWZ128((uint32_t)((warp_m * 32 + mi * 16 + lrow) * 128 + lcol16 * 16));
    #pragma unroll
    for (int nj = 0; nj < 4; nj++)
        bswz[nj] = SWZ128((uint32_t)((warp_n * 64 + nj * 16 + lrow) * 128 + lcol16 * 16));

    auto load_stage = [&](int kit) {
        const int buf = kit % STAGES;
        const uint32_t sA = dyn_base + buf * STAGE_BYTES;
        const uint32_t sB = sA + TILE_BYTES;
        const int k0 = kit * BK;
        #pragma unroll
        for (int r = 0; r < 4; r++) {
            const int idx = tid + r * 256;
            const int row = idx >> 3;
            const int c16 = idx & 7;
            const uint32_t soff = SWZ128((uint32_t)(row * 128 + c16 * 16));
            cp_async16(sA + soff, &g_alphaB[(size_t)(m0 + row) * NUM_STATE + k0 + c16 * 8]);
            cp_async16(sB + soff, &g_matT [(size_t)(n0 + row) * NUM_STATE + k0 + c16 * 8]);
        }
    };

    float c[2][8][4];
    #pragma unroll
    for (int i = 0; i < 2; i++)
        #pragma unroll
        for (int j = 0; j < 8; j++)
            #pragma unroll
            for (int k = 0; k < 4; k++) c[i][j][k] = 0.f;

    uint32_t af[2][4], bf[4][4];

    auto ldsm_ks = [&](uint32_t sA, uint32_t sB, int ks) {
        const uint32_t kx = (uint32_t)(ks << 5);
        #pragma unroll
        for (int mi = 0; mi < 2; mi++) ldsm4(af[mi], sA + (aswz[mi] ^ kx));
        #pragma unroll
        for (int nj = 0; nj < 4; nj++) ldsm4(bf[nj], sB + (bswz[nj] ^ kx));
    };
    // ldmatrix x4 register layout:
    //   bf[nj][0] = (n 0-7 , k 0-7)   bf[nj][1] = (n 8-15, k 0-7)
    //   bf[nj][2] = (n 0-7 , k 8-15)  bf[nj][3] = (n 8-15, k 8-15)
    auto mma_all = [&]() {
        #pragma unroll
        for (int mi = 0; mi < 2; mi++)
            #pragma unroll
            for (int nj = 0; nj < 4; nj++) {
                mma_bf16(c[mi][nj * 2 + 0], af[mi], bf[nj][0], bf[nj][2]);
                mma_bf16(c[mi][nj * 2 + 1], af[mi], bf[nj][1], bf[nj][3]);
            }
    };

    #pragma unroll
    for (int i = 0; i < STAGES - 1; i++) { load_stage(i); CP_COMMIT(); }

    for (int kit = 0; kit < KITERS; kit++) {
        cp_wait<STAGES - 2>();
        __syncthreads();

        const uint32_t sA = dyn_base + (kit % STAGES) * STAGE_BYTES;
        const uint32_t sB = sA + TILE_BYTES;

        ldsm_ks(sA, sB, 0);
        if (kit + STAGES - 1 < KITERS) load_stage(kit + STAGES - 1);
        CP_COMMIT();

        #pragma unroll
        for (int ks = 0; ks < BK / 16; ks++) {
            mma_all();
            if (ks < BK / 16 - 1) ldsm_ks(sA, sB, ks + 1);
        }
    }

    const int r_base = m0 + warp_m * 32 + (lane >> 2);
    const int c_base = n0 + warp_n * 64 + (lane & 3) * 2;
    #pragma unroll
    for (int mi = 0; mi < 2; mi++) {
        #pragma unroll
        for (int ni = 0; ni < 8; ni++) {
            float* p0 = out + (size_t)(r_base + mi * 16) * NUM_STATE + c_base + ni * 8;
            float* p1 = out + (size_t)(r_base + mi * 16 + 8) * NUM_STATE + c_base + ni * 8;
            *reinterpret_cast<float2*>(p0) = make_float2(c[mi][ni][0], c[mi][ni][1]);
            *reinterpret_cast<float2*>(p1) = make_float2(c[mi][ni][2], c[mi][ni][3]);
        }
    }
}

// ---------------------------------------------------------------------------
// Launch
// ---------------------------------------------------------------------------
extern "C" void kernel_launch(void* const* d_in, const int* in_sizes, int n_in,
                              void* d_out, int out_size) {
    (void)in_sizes; (void)n_in; (void)out_size;
    // metadata order: state_embeddings(0, unused), alpha(1), context(2, unused), utm(3)
    const float* alpha = (const float*)d_in[1];
    const float* utm   = (const float*)d_in[3];
    float* out = (float*)d_out;

    cudaFuncSetAttribute(gemm_kernel, cudaFuncAttributeMaxDynamicSharedMemorySize, DYN_SMEM);

    zero_flags_kernel<<<1, NGROUPS>>>();
    prep_kernel<<<PREP_BLOCKS, 256>>>(utm, alpha);
    gemm_kernel<<<(BATCH / BM) * (NUM_STATE / BN), 256, DYN_SMEM>>>(out);
}

// round 11
// speedup vs baseline: 2.3337x; 1.1099x over previous
#include <cuda_runtime.h>
#include <cuda_bf16.h>
#include <cstdint>
#include <cstddef>

// Problem constants
#define NUM_STATE 2048
#define BATCH     4096

// ---------------------------------------------------------------------------
// Scratch (device globals; no cudaMalloc allowed)
// ---------------------------------------------------------------------------
__device__ __align__(16) __nv_bfloat16 g_alphaB[(size_t)BATCH * NUM_STATE];     // 16 MB
__device__ __align__(16) __nv_bfloat16 g_matT[(size_t)NUM_STATE * NUM_STATE];   // 8 MB, matT[t][s] = mat[s][t]
__device__ float g_rmax[NUM_STATE];
__device__ float g_rinv[NUM_STATE];

// ---------------------------------------------------------------------------
// Helpers
// ---------------------------------------------------------------------------
__device__ __forceinline__ uint32_t smem_u32(const void* p) {
    uint32_t a;
    asm("{ .reg .u64 t; cvta.to.shared.u64 t, %1; cvt.u32.u64 %0, t; }" : "=r"(a) : "l"(p));
    return a;
}

#define SWZ128(off) ((off) ^ (((off) >> 3) & 0x70))

__device__ __forceinline__ void cp_async16(uint32_t s, const void* g) {
    asm volatile("cp.async.cg.shared.global [%0], [%1], 16;" :: "r"(s), "l"(g) : "memory");
}
#define CP_COMMIT() asm volatile("cp.async.commit_group;" ::: "memory")
template <int N>
__device__ __forceinline__ void cp_wait() {
    asm volatile("cp.async.wait_group %0;" :: "n"(N) : "memory");
}

__device__ __forceinline__ void ldsm4(uint32_t* r, uint32_t addr) {
    asm volatile("ldmatrix.sync.aligned.m8n8.x4.shared.b16 {%0,%1,%2,%3}, [%4];"
                 : "=r"(r[0]), "=r"(r[1]), "=r"(r[2]), "=r"(r[3]) : "r"(addr));
}

__device__ __forceinline__ void mma_bf16(float* c, const uint32_t* a,
                                         uint32_t b0, uint32_t b1) {
    asm volatile(
        "mma.sync.aligned.m16n8k16.row.col.f32.bf16.bf16.f32 "
        "{%0,%1,%2,%3}, {%4,%5,%6,%7}, {%8,%9}, {%0,%1,%2,%3};"
        : "+f"(c[0]), "+f"(c[1]), "+f"(c[2]), "+f"(c[3])
        : "r"(a[0]), "r"(a[1]), "r"(a[2]), "r"(a[3]), "r"(b0), "r"(b1));
}

// ---------------------------------------------------------------------------
// Alpha fp32 -> bf16 conversion chunk: one block converts 8192 contiguous
// elements (256 threads x 8 float4, all loads independent -> MLP 8).
// ---------------------------------------------------------------------------
static constexpr int CVT_CHUNK = 8192;
static constexpr int CVT_CHUNKS_TOTAL = (BATCH * NUM_STATE) / CVT_CHUNK;  // 1024
static constexpr int CVT1_CHUNKS = 576;                                    // in prep1
static constexpr int CVT2_CHUNKS = CVT_CHUNKS_TOTAL - CVT1_CHUNKS;         // 448 in prep2
static constexpr int STATS_BLOCKS = NUM_STATE;                             // 2048
static constexpr int BUILD_BLOCKS = (NUM_STATE / 32) * (NUM_STATE / 32);   // 4096

__device__ __forceinline__ void cvt_alpha_chunk(const float* __restrict__ a, int cb) {
    const size_t base = (size_t)cb * CVT_CHUNK + threadIdx.x * 4;
    float4 v[8];
    #pragma unroll
    for (int j = 0; j < 8; j++)
        v[j] = *reinterpret_cast<const float4*>(a + base + (size_t)j * 1024);
    #pragma unroll
    for (int j = 0; j < 8; j++) {
        __nv_bfloat162 p0 = __floats2bfloat162_rn(v[j].x, v[j].y);
        __nv_bfloat162 p1 = __floats2bfloat162_rn(v[j].z, v[j].w);
        uint2 w;
        w.x = *reinterpret_cast<uint32_t*>(&p0);
        w.y = *reinterpret_cast<uint32_t*>(&p1);
        *reinterpret_cast<uint2*>(&g_alphaB[base + (size_t)j * 1024]) = w;
    }
}

// ---------------------------------------------------------------------------
// Prep kernel 1: [blocks 0..2047] per-row softmax stats, register-resident
// row (8 elements/thread, MLP 8); [blocks 2048..] cvt chunks.  (R7 verbatim)
// ---------------------------------------------------------------------------
__global__ __launch_bounds__(256) void prep1_kernel(const float* __restrict__ utm,
                                                    const float* __restrict__ alpha) {
    if (blockIdx.x >= STATS_BLOCKS) {
        cvt_alpha_chunk(alpha, blockIdx.x - STATS_BLOCKS);
        return;
    }
    const int s = blockIdx.x;
    const float* row = utm + (size_t)s * (NUM_STATE - 1);
    const int tid = threadIdx.x;
    const int base = tid * 8;

    __shared__ float red[8];
    __shared__ float s_mx;

    float v[8];
    #pragma unroll
    for (int j = 0; j < 8; j++)
        v[j] = (base + j < NUM_STATE - 1) ? row[base + j] : -3.4e38f;

    float mx = v[0];
    #pragma unroll
    for (int j = 1; j < 8; j++) mx = fmaxf(mx, v[j]);
    #pragma unroll
    for (int o = 16; o; o >>= 1) mx = fmaxf(mx, __shfl_xor_sync(0xffffffffu, mx, o));
    if ((tid & 31) == 0) red[tid >> 5] = mx;
    __syncthreads();
    if (tid == 0) {
        float m = red[0];
        #pragma unroll
        for (int i = 1; i < 8; i++) m = fmaxf(m, red[i]);
        s_mx = m;
    }
    __syncthreads();
    const float m = s_mx;

    float sm = 0.f;
    #pragma unroll
    for (int j = 0; j < 8; j++)
        if (base + j < NUM_STATE - 1) sm += __expf(v[j] - m);
    #pragma unroll
    for (int o = 16; o; o >>= 1) sm += __shfl_xor_sync(0xffffffffu, sm, o);
    if ((tid & 31) == 0) red[tid >> 5] = sm;
    __syncthreads();
    if (tid == 0) {
        float t = 0.f;
        #pragma unroll
        for (int i = 0; i < 8; i++) t += red[i];
        g_rmax[s] = m;
        g_rinv[s] = 1.0f / t;
    }
}

// ---------------------------------------------------------------------------
// Prep kernel 2: [blocks 0..4095] build matT tiles; [4096..] cvt chunks.
// mat[s][t] = (t==s) ? 0 : exp(u[s][t-(t>s)] - max[s]) * inv[s]  (R7 verbatim)
// ---------------------------------------------------------------------------
__global__ __launch_bounds__(256) void prep2_kernel(const float* __restrict__ utm,
                                                    const float* __restrict__ alpha) {
    if (blockIdx.x >= BUILD_BLOCKS) {
        cvt_alpha_chunk(alpha, CVT1_CHUNKS + (int)blockIdx.x - BUILD_BLOCKS);
        return;
    }
    const int s0 = (blockIdx.x & 63) * 32;
    const int t0 = (blockIdx.x >> 6) * 32;
    const int tl = threadIdx.x;
    const int tx = tl & 31;        // -> s
    const int ty = tl >> 5;        // -> t (x4)

    __shared__ float su[32][34];   // su[sy][cx] = u[s0+sy][t0-1+cx]

    for (int i = tl; i < 32 * 33; i += 256) {
        const int sy = i / 33;
        const int cx = i % 33;
        const int c = t0 - 1 + cx;
        su[sy][cx] = (c >= 0 && c < NUM_STATE - 1)
                       ? utm[(size_t)(s0 + sy) * (NUM_STATE - 1) + c] : 0.f;
    }
    __syncthreads();

    const int s = s0 + tx;
    const float mx = g_rmax[s];
    const float inv = g_rinv[s];

    #pragma unroll
    for (int k = 0; k < 4; k++) {
        const int yy = ty + 8 * k;
        const int t = t0 + yy;
        float v;
        if (t == s) {
            v = 0.f;
        } else {
            const int cx = yy + 1 - (t > s);   // = (t - (t>s)) - (t0-1)
            v = __expf(su[tx][cx] - mx) * inv;
        }
        g_matT[(size_t)t * NUM_STATE + s] = __float2bfloat16(v);
    }
}

// ---------------------------------------------------------------------------
// GEMM: mma.sync bf16, C[4096,2048] = A @ matT^T
// NEW in R11: CTA tile 64x128x64 -> 1024 tiles. SM tile-rate is residency-
// independent (saturated by one CTA, R3 vs R5 evidence), so makespan is set
// by max-tiles-per-SM: ceil(1024/148)=7 vs avg 6.92 (1.2% tail) instead of
// ceil(512/148)=4 vs 3.46 (15.6% tail).
// 8 warps: warp_m in {0,1} x warp_n in {0..3}, warp tile 32x32.
// ---------------------------------------------------------------------------
static constexpr int BM = 64, BN = 128, BK = 64, STAGES = 3;
static constexpr int KITERS = NUM_STATE / BK;                       // 32
static constexpr int A_TILE_BYTES = BM * BK * 2;                    // 8192
static constexpr int B_TILE_BYTES = BN * BK * 2;                    // 16384
static constexpr int STAGE_BYTES = A_TILE_BYTES + B_TILE_BYTES;     // 24576
static constexpr int DYN_SMEM = STAGES * STAGE_BYTES + 1024;        // 74752
static constexpr int GEMM_TILES = (BATCH / BM) * (NUM_STATE / BN);  // 1024

__global__ __launch_bounds__(256, 2) void gemm_kernel(float* __restrict__ out) {
    extern __shared__ char dsm[];
    const uint32_t dyn_base = (smem_u32(dsm) + 1023u) & ~1023u;

    const int tid = threadIdx.x;
    const int wid = tid >> 5;
    const int lane = tid & 31;

    const int tile = blockIdx.x;
    const int n0 = (tile & 15) * BN;      // consecutive bids share the A m-tile
    const int m0 = (tile >> 4) * BM;

    const int warp_m = wid & 1;           // 2 slices of 32 rows
    const int warp_n = wid >> 1;          // 4 slices of 32 cols

    const int lrow = lane & 15;
    const int lcol16 = (lane >> 4) & 1;

    // Precomputed swizzled ldsm base offsets; per-ks address is base ^ (ks*32)
    uint32_t aswz[2], bswz[2];
    #pragma unroll
    for (int mi = 0; mi < 2; mi++)
        aswz[mi] = SWZ128((uint32_t)((warp_m * 32 + mi * 16 + lrow) * 128 + lcol16 * 16));
    #pragma unroll
    for (int nj = 0; nj < 2; nj++)
        bswz[nj] = SWZ128((uint32_t)((warp_n * 32 + nj * 16 + lrow) * 128 + lcol16 * 16));

    auto load_stage = [&](int kit) {
        const int buf = kit % STAGES;
        const uint32_t sA = dyn_base + buf * STAGE_BYTES;
        const uint32_t sB = sA + A_TILE_BYTES;
        const int k0 = kit * BK;
        #pragma unroll
        for (int r = 0; r < 6; r++) {
            const int idx = tid + r * 256;       // 0..1535
            const int row = idx >> 3;            // 0..191: 0-63 A, 64-191 B
            const int c16 = idx & 7;
            if (row < BM) {
                const uint32_t soff = SWZ128((uint32_t)(row * 128 + c16 * 16));
                cp_async16(sA + soff,
                           &g_alphaB[(size_t)(m0 + row) * NUM_STATE + k0 + c16 * 8]);
            } else {
                const int rb = row - BM;
                const uint32_t soff = SWZ128((uint32_t)(rb * 128 + c16 * 16));
                cp_async16(sB + soff,
                           &g_matT[(size_t)(n0 + rb) * NUM_STATE + k0 + c16 * 8]);
            }
        }
    };

    float c[2][4][4];
    #pragma unroll
    for (int i = 0; i < 2; i++)
        #pragma unroll
        for (int j = 0; j < 4; j++)
            #pragma unroll
            for (int k = 0; k < 4; k++) c[i][j][k] = 0.f;

    uint32_t af[2][4], bf[2][4];

    auto ldsm_ks = [&](uint32_t sA, uint32_t sB, int ks) {
        const uint32_t kx = (uint32_t)(ks << 5);
        #pragma unroll
        for (int mi = 0; mi < 2; mi++) ldsm4(af[mi], sA + (aswz[mi] ^ kx));
        #pragma unroll
        for (int nj = 0; nj < 2; nj++) ldsm4(bf[nj], sB + (bswz[nj] ^ kx));
    };
    // ldmatrix x4 register layout:
    //   bf[nj][0] = (n 0-7 , k 0-7)   bf[nj][1] = (n 8-15, k 0-7)
    //   bf[nj][2] = (n 0-7 , k 8-15)  bf[nj][3] = (n 8-15, k 8-15)
    auto mma_all = [&]() {
        #pragma unroll
        for (int mi = 0; mi < 2; mi++)
            #pragma unroll
            for (int nj = 0; nj < 2; nj++) {
                mma_bf16(c[mi][nj * 2 + 0], af[mi], bf[nj][0], bf[nj][2]);
                mma_bf16(c[mi][nj * 2 + 1], af[mi], bf[nj][1], bf[nj][3]);
            }
    };

    #pragma unroll
    for (int i = 0; i < STAGES - 1; i++) { load_stage(i); CP_COMMIT(); }

    for (int kit = 0; kit < KITERS; kit++) {
        cp_wait<STAGES - 2>();
        __syncthreads();

        const uint32_t sA = dyn_base + (kit % STAGES) * STAGE_BYTES;
        const uint32_t sB = sA + A_TILE_BYTES;

        ldsm_ks(sA, sB, 0);
        if (kit + STAGES - 1 < KITERS) load_stage(kit + STAGES - 1);
        CP_COMMIT();   // unconditional: keeps wait_group accounting exact in the tail

        #pragma unroll
        for (int ks = 0; ks < BK / 16; ks++) {
            mma_all();
            if (ks < BK / 16 - 1) ldsm_ks(sA, sB, ks + 1);
        }
    }

    // Epilogue: direct float2 stores (warp 32x32 tile)
    const int r_base = m0 + warp_m * 32 + (lane >> 2);
    const int c_base = n0 + warp_n * 32 + (lane & 3) * 2;
    #pragma unroll
    for (int mi = 0; mi < 2; mi++) {
        #pragma unroll
        for (int ni = 0; ni < 4; ni++) {
            float* p0 = out + (size_t)(r_base + mi * 16) * NUM_STATE + c_base + ni * 8;
            float* p1 = out + (size_t)(r_base + mi * 16 + 8) * NUM_STATE + c_base + ni * 8;
            *reinterpret_cast<float2*>(p0) = make_float2(c[mi][ni][0], c[mi][ni][1]);
            *reinterpret_cast<float2*>(p1) = make_float2(c[mi][ni][2], c[mi][ni][3]);
        }
    }
}

// ---------------------------------------------------------------------------
// Launch
// ---------------------------------------------------------------------------
extern "C" void kernel_launch(void* const* d_in, const int* in_sizes, int n_in,
                              void* d_out, int out_size) {
    (void)in_sizes; (void)n_in; (void)out_size;
    // metadata order: state_embeddings(0, unused), alpha(1), context(2, unused), utm(3)
    const float* alpha = (const float*)d_in[1];
    const float* utm   = (const float*)d_in[3];
    float* out = (float*)d_out;

    cudaFuncSetAttribute(gemm_kernel, cudaFuncAttributeMaxDynamicSharedMemorySize, DYN_SMEM);

    prep1_kernel<<<STATS_BLOCKS + CVT1_CHUNKS, 256>>>(utm, alpha);
    prep2_kernel<<<BUILD_BLOCKS + CVT2_CHUNKS, 256>>>(utm, alpha);
    gemm_kernel<<<GEMM_TILES, 256, DYN_SMEM>>>(out);
}